// round 14
// baseline (speedup 1.0000x reference)
#include <cuda_runtime.h>
#include <cuda_fp16.h>
#include <cstdint>

#define DT_F (1.0f/64.0f)
#define NSTEPS 64
#define NK 32
#define RTOT 16384
#define VOX_PER_PRIM 4096

#define CONV_BLOCKS 512                 // cell-pack: 512 blocks x 256 thr = 131072 cells
#define PREP_RAYS_PER_BLOCK 8
#define PREP_BLOCKS (RTOT / PREP_RAYS_PER_BLOCK)   // 2048
#define SETUP_BLOCKS (CONV_BLOCKS + PREP_BLOCKS)

#define MAIN_NTHREADS 128
#define MAIN_BLOCKS 1480                // ~10 blocks/SM x 148 SMs; extras exit fast

// cell-packed fp16 template: [k][cell] -> 4 x uint4 (64 B per cell)
//   q0 = corners (z ,y ,x),(z ,y ,x+1)   q1 = (z ,y+1,x),(z ,y+1,x+1)
//   q2 = corners (z+1,y ,x),(z+1,y ,x+1) q3 = (z+1,y+1,x),(z+1,y+1,x+1)
__device__ __align__(16) uint4 g_tplc[NK * VOX_PER_PRIM * 4];   // 8 MB

// per-ray compacted hit lists
__device__ __align__(16) float4 g_hitA[RTOT * NK];   // (a0,a1,a2, bitcast k)
__device__ __align__(16) float4 g_hitB[RTOT * NK];   // (b0,b1,b2, bitcast sLo|sHi<<16)
__device__ int g_hitcnt[RTOT];
__device__ int g_next;                                // dynamic ray ticket

__device__ __forceinline__ uint2 pack_corner(const float* tk, int z, int y, int x)
{
    const int v = (z*16 + y)*16 + x;
    const half2 h0 = __floats2half2_rn(tk[v],        tk[v + 4096]);
    const half2 h1 = __floats2half2_rn(tk[v + 8192], tk[v + 12288]);
    uint2 q;
    q.x = *reinterpret_cast<const unsigned int*>(&h0);
    q.y = *reinterpret_cast<const unsigned int*>(&h1);
    return q;
}

// Fused setup: blocks [0,CONV_BLOCKS) cell-pack the template; the rest run per-ray prep.
__global__ void __launch_bounds__(256)
setup_kernel(const float* __restrict__ tpl,
             const float* __restrict__ raypos,
             const float* __restrict__ raydir,
             const float* __restrict__ tminmax,
             const float* __restrict__ primpos,
             const float* __restrict__ primrot,
             const float* __restrict__ primscale)
{
    if (blockIdx.x == 0 && threadIdx.x == 0) g_next = 0;   // reset ticket each launch

    if (blockIdx.x < CONV_BLOCKS) {
        const int idx  = blockIdx.x * 256 + threadIdx.x;   // 0 .. 131071
        const int k    = idx >> 12;
        const int cell = idx & 4095;
        const int ix = cell & 15, iy = (cell >> 4) & 15, iz = cell >> 8;
        const int x1 = min(ix + 1, 15), y1 = min(iy + 1, 15), z1 = min(iz + 1, 15);
        const float* tk = tpl + (size_t)k * 4 * VOX_PER_PRIM;

        uint4 q0, q1, q2, q3;
        { uint2 a = pack_corner(tk, iz, iy, ix), b = pack_corner(tk, iz, iy, x1);
          q0 = make_uint4(a.x, a.y, b.x, b.y); }
        { uint2 a = pack_corner(tk, iz, y1, ix), b = pack_corner(tk, iz, y1, x1);
          q1 = make_uint4(a.x, a.y, b.x, b.y); }
        { uint2 a = pack_corner(tk, z1, iy, ix), b = pack_corner(tk, z1, iy, x1);
          q2 = make_uint4(a.x, a.y, b.x, b.y); }
        { uint2 a = pack_corner(tk, z1, y1, ix), b = pack_corner(tk, z1, y1, x1);
          q3 = make_uint4(a.x, a.y, b.x, b.y); }

        uint4* dst = g_tplc + (size_t)idx * 4;
        dst[0] = q0; dst[1] = q1; dst[2] = q2; dst[3] = q3;
        return;
    }

    // ---- prep: one warp per ray; lane = prim. Linearize + slab cull + compact. ----
    const int lane = threadIdx.x & 31;
    const int w    = threadIdx.x >> 5;
    const int r    = (blockIdx.x - CONV_BLOCKS) * PREP_RAYS_PER_BLOCK + w;
    const int k    = lane;                       // NK == 32

    const float rpx = raypos[3*r+0], rpy = raypos[3*r+1], rpz = raypos[3*r+2];
    const float rdx = raydir[3*r+0], rdy = raydir[3*r+1], rdz = raydir[3*r+2];
    const float tmn = tminmax[2*r+0];

    const float ppx = primpos[3*k+0], ppy = primpos[3*k+1], ppz = primpos[3*k+2];
    float a[3], b[3];
    #pragma unroll
    for (int i = 0; i < 3; i++) {
        const float s  = primscale[3*k+i];
        const float m0 = s * primrot[9*k+3*i+0];
        const float m1 = s * primrot[9*k+3*i+1];
        const float m2 = s * primrot[9*k+3*i+2];
        const float c  = m0*ppx + m1*ppy + m2*ppz;
        a[i] = fmaf(m0, rdx, fmaf(m1, rdy, m2*rdz));
        b[i] = fmaf(m0, rpx, fmaf(m1, rpy, fmaf(m2, rpz, -c)));
    }

    const float EPS = 1e-5f;
    const float i0 = 1.f / a[0], i1 = 1.f / a[1], i2 = 1.f / a[2];
    const float u0 = (-1.f - EPS - b[0]) * i0, v0 = (1.f + EPS - b[0]) * i0;
    const float u1 = (-1.f - EPS - b[1]) * i1, v1 = (1.f + EPS - b[1]) * i1;
    const float u2 = (-1.f - EPS - b[2]) * i2, v2 = (1.f + EPS - b[2]) * i2;
    const float tlo = fmaxf(fmaxf(fminf(u0, v0), fminf(u1, v1)), fminf(u2, v2));
    const float thi = fminf(fminf(fmaxf(u0, v0), fmaxf(u1, v1)), fmaxf(u2, v2));

    const float tray_hi = fmaf(63.f, DT_F, tmn);
    const bool hit = !(thi < tmn || tlo > tray_hi || tlo > thi);

    const unsigned bal = __ballot_sync(0xffffffffu, hit);
    if (hit) {
        int sLo = (int)floorf((tlo - tmn) * 64.f);
        int sHi = (int)ceilf((thi - tmn) * 64.f);
        sLo = max(sLo, 0);
        sHi = min(sHi, 63);
        const int slot = __popc(bal & ((1u << lane) - 1u));
        g_hitA[r*NK + slot] = make_float4(a[0], a[1], a[2], __int_as_float(k));
        g_hitB[r*NK + slot] = make_float4(b[0], b[1], b[2],
                                          __int_as_float(sLo | (sHi << 16)));
    }
    if (lane == 0) g_hitcnt[r] = __popc(bal);
}

__device__ __forceinline__ half2 h2_of(uint32_t u) { return *reinterpret_cast<const half2*>(&u); }

__global__ void __launch_bounds__(MAIN_NTHREADS)
raymarch_kernel(const float* __restrict__ tminmax,
                float* __restrict__ out)
{
    const int lane = threadIdx.x & 31;

    for (;;) {
        int r;
        if (lane == 0) r = atomicAdd(&g_next, 1);
        r = __shfl_sync(0xffffffffu, r, 0);
        if (r >= RTOT) break;

        const float tmn = tminmax[2*r+0], tmx = tminmax[2*r+1];

        // Thread owns steps (lane) and (lane+32): tA, tB
        const float tA = fmaf((float)lane, DT_F, tmn);
        const float tB = fmaf((float)(lane + 32), DT_F, tmn);

        float4 acc[2];
        acc[0] = make_float4(0.f, 0.f, 0.f, 0.f);
        acc[1] = make_float4(0.f, 0.f, 0.f, 0.f);

        const int cnt = g_hitcnt[r];

        for (int s = 0; s < cnt; s++) {
            const float4 A = __ldg(&g_hitA[r*NK + s]);      // broadcast (warp-uniform)
            const float4 B = __ldg(&g_hitB[r*NK + s]);
            const int k = __float_as_int(A.w);
            const int rng = __float_as_int(B.w);
            const int sLo = rng & 0xffff;
            const int sHi = rng >> 16;
            const uint4* __restrict__ tpl = g_tplc + ((size_t)k << 14);

            #pragma unroll
            for (int j = 0; j < 2; j++) {
                const int step = lane + 32*j;
                if (step < sLo || step > sHi) continue;     // cheap integer gate
                const float t = (j == 0) ? tA : tB;

                const float y0 = fmaf(t, A.x, B.x);
                const float y1 = fmaf(t, A.y, B.y);
                const float y2 = fmaf(t, A.z, B.z);

                if (fabsf(y0) <= 1.f && fabsf(y1) <= 1.f && fabsf(y2) <= 1.f) {
                    const float gz = fmaf(y0, 7.5f, 7.5f);
                    const float gy = fmaf(y1, 7.5f, 7.5f);
                    const float gx = fmaf(y2, 7.5f, 7.5f);
                    const float fz0 = fminf(floorf(gz), 14.f);
                    const float fy0 = fminf(floorf(gy), 14.f);
                    const float fx0 = fminf(floorf(gx), 14.f);
                    const int iz = (int)fz0, iy = (int)fy0, ix = (int)fx0;
                    const float fz = fminf(gz - fz0, 1.f);
                    const float fy = fminf(gy - fy0, 1.f);
                    const float fx = fminf(gx - fx0, 1.f);

                    // one 64-byte cell: 4 consecutive LDG.128
                    const uint4* cp = tpl + ((size_t)((iz*16 + iy)*16 + ix) << 2);
                    const uint4 p00 = __ldg(cp);        // (z ,y )  x-pair
                    const uint4 p01 = __ldg(cp + 1);    // (z ,y1)  x-pair
                    const uint4 p10 = __ldg(cp + 2);    // (z1,y )  x-pair
                    const uint4 p11 = __ldg(cp + 3);    // (z1,y1)  x-pair

                    const float wz0 = 1.f - fz, wy0 = 1.f - fy, wx0 = 1.f - fx;
                    const float w00 = wz0*wy0, w01 = wz0*fy, w10 = fz*wy0, w11 = fz*fy;

                    const half2 h000 = __float2half2_rn(w00*wx0);
                    const half2 h001 = __float2half2_rn(w00*fx);
                    const half2 h010 = __float2half2_rn(w01*wx0);
                    const half2 h011 = __float2half2_rn(w01*fx);
                    const half2 h100 = __float2half2_rn(w10*wx0);
                    const half2 h101 = __float2half2_rn(w10*fx);
                    const half2 h110 = __float2half2_rn(w11*wx0);
                    const half2 h111 = __float2half2_rn(w11*fx);

                    // 8-corner trilinear in packed fp16 (rg and ba lanes)
                    half2 srg = __hmul2(h000, h2_of(p00.x));
                    half2 sba = __hmul2(h000, h2_of(p00.y));
                    srg = __hfma2(h001, h2_of(p00.z), srg);
                    sba = __hfma2(h001, h2_of(p00.w), sba);
                    srg = __hfma2(h010, h2_of(p01.x), srg);
                    sba = __hfma2(h010, h2_of(p01.y), sba);
                    srg = __hfma2(h011, h2_of(p01.z), srg);
                    sba = __hfma2(h011, h2_of(p01.w), sba);
                    srg = __hfma2(h100, h2_of(p10.x), srg);
                    sba = __hfma2(h100, h2_of(p10.y), sba);
                    srg = __hfma2(h101, h2_of(p10.z), srg);
                    sba = __hfma2(h101, h2_of(p10.w), sba);
                    srg = __hfma2(h110, h2_of(p11.x), srg);
                    sba = __hfma2(h110, h2_of(p11.y), sba);
                    srg = __hfma2(h111, h2_of(p11.z), srg);
                    sba = __hfma2(h111, h2_of(p11.w), sba);

                    const float2 frg = __half22float2(srg);
                    const float2 fba = __half22float2(sba);
                    acc[j].x += frg.x;
                    acc[j].y += frg.y;
                    acc[j].z += fba.x;
                    acc[j].w += fba.y;
                }
            }
        }

        // ---- Composite: alpha_i = min(prefix_i, 1); contrib = alpha_i - alpha_{i-1} ----
        const float sA = (tA < tmx) ? acc[0].w * DT_F : 0.f;
        const float sB = (tB < tmx) ? acc[1].w * DT_F : 0.f;

        float scanA = sA;
        #pragma unroll
        for (int d = 1; d < 32; d <<= 1) {
            const float v = __shfl_up_sync(0xffffffffu, scanA, d);
            if (lane >= d) scanA += v;
        }
        const float totA = __shfl_sync(0xffffffffu, scanA, 31);

        float scanB = sB;
        #pragma unroll
        for (int d = 1; d < 32; d <<= 1) {
            const float v = __shfl_up_sync(0xffffffffu, scanB, d);
            if (lane >= d) scanB += v;
        }

        const float PA = scanA;                 // inclusive prefix at step lane
        const float PB = totA + scanB;          // inclusive prefix at step lane+32

        const float contribA = fminf(PA, 1.f) - fminf(PA - sA, 1.f);
        const float contribB = fminf(PB, 1.f) - fminf(PB - sB, 1.f);

        float rgbx = acc[0].x * contribA + acc[1].x * contribB;
        float rgby = acc[0].y * contribA + acc[1].y * contribB;
        float rgbz = acc[0].z * contribA + acc[1].z * contribB;

        #pragma unroll
        for (int d = 16; d >= 1; d >>= 1) {
            rgbx += __shfl_xor_sync(0xffffffffu, rgbx, d);
            rgby += __shfl_xor_sync(0xffffffffu, rgby, d);
            rgbz += __shfl_xor_sync(0xffffffffu, rgbz, d);
        }
        const float alpha_final = fminf(totA + __shfl_sync(0xffffffffu, scanB, 31), 1.f);

        if (lane == 0) {
            // out = [rayrgb (3*R)] [rayalpha (R)] [rayrgba (4*R)]
            out[0*RTOT + r] = rgbx;
            out[1*RTOT + r] = rgby;
            out[2*RTOT + r] = rgbz;
            out[3*RTOT + r] = alpha_final;
            out[4*RTOT + r] = rgbx;
            out[5*RTOT + r] = rgby;
            out[6*RTOT + r] = rgbz;
            out[7*RTOT + r] = alpha_final;
        }
    }
}

extern "C" void kernel_launch(void* const* d_in, const int* in_sizes, int n_in,
                              void* d_out, int out_size)
{
    const float* raypos    = (const float*)d_in[0];
    const float* raydir    = (const float*)d_in[1];
    const float* tminmax   = (const float*)d_in[2];
    const float* primpos   = (const float*)d_in[3];
    const float* primrot   = (const float*)d_in[4];
    const float* primscale = (const float*)d_in[5];
    const float* tpl       = (const float*)d_in[6];
    float* out = (float*)d_out;

    setup_kernel<<<SETUP_BLOCKS, 256>>>(tpl, raypos, raydir, tminmax,
                                        primpos, primrot, primscale);
    raymarch_kernel<<<MAIN_BLOCKS, MAIN_NTHREADS>>>(tminmax, out);
}